// round 9
// baseline (speedup 1.0000x reference)
#include <cuda_runtime.h>

#define N_EMB   512
#define EMB_D   64
#define HWSZ    4096
#define NTOK    131072
#define TPB     256
#define TOKS_PER_CHUNK (TPB * 2)          // T=2 tokens per thread
#define NCHUNK  (NTOK / TOKS_PER_CHUNK)   // 256
#define GRID_A  148
#define NREP    8

// Output packing (float32, reference tuple order)
#define OFF_RES 0ULL
#define OFF_ARG 8388608ULL
#define OFF_W   8519680ULL
#define OFF_CS  8552448ULL
#define OFF_EA  8552960ULL

#define SMEM_BYTES ((N_EMB * EMB_D + N_EMB) * 4)   // 133120 B

__device__ float g_histR[NREP][N_EMB];
__device__ float g_esumR[NREP][EMB_D * N_EMB];
__device__ float g_ww[N_EMB];
__device__ float g_wt[N_EMB * EMB_D];   // weight transposed: [j][d]
__device__ unsigned int g_work;
__device__ unsigned int g_done;

__device__ __forceinline__ unsigned long long ffma2(unsigned long long a,
                                                    unsigned long long b,
                                                    unsigned long long c) {
    unsigned long long d;
    asm("fma.rn.f32x2 %0, %1, %2, %3;" : "=l"(d) : "l"(a), "l"(b), "l"(c));
    return d;
}

__device__ __forceinline__ unsigned long long fadd2(unsigned long long a,
                                                    unsigned long long b) {
    unsigned long long d;
    asm("add.rn.f32x2 %0, %1, %2;" : "=l"(d) : "l"(a), "l"(b));
    return d;
}

__device__ __forceinline__ unsigned long long pack2(float lo, float hi) {
    unsigned long long r;
    asm("mov.b64 %0, {%1, %2};" : "=l"(r)
        : "r"(__float_as_uint(lo)), "r"(__float_as_uint(hi)));
    return r;
}

__device__ __forceinline__ void unpack2(unsigned long long v, float& lo, float& hi) {
    unsigned int a, b;
    asm("mov.b64 {%0, %1}, %2;" : "=r"(a), "=r"(b) : "l"(v));
    lo = __uint_as_float(a);
    hi = __uint_as_float(b);
}

// argmin update with pred-as-data (FSETP->SEL, 4cyc) instead of @P guard (13cyc)
__device__ __forceinline__ void amin_upd(float d, int j, float& best, int& bi) {
    float old = best;
    best = fminf(best, d);             // FMNMX, fma/alu pipe, lat 4
    bi   = (d < old) ? j : bi;         // FSETP + SEL (pred-as-data)
}

// ---------------------------------------------------------------------------
// prep: zero replicated scratch, transpose weight, ||w||^2, reset counters
// ---------------------------------------------------------------------------
__global__ void prep_kernel(const float* __restrict__ w) {
    int idx = blockIdx.x * blockDim.x + threadIdx.x;   // 0..32767
    if (idx == 0) { g_work = 0u; g_done = 0u; }
    if (idx < EMB_D * N_EMB) {
        #pragma unroll
        for (int r = 0; r < NREP; r++) g_esumR[r][idx] = 0.0f;
        int j = idx >> 6;
        int d = idx & 63;
        g_wt[idx] = w[d * N_EMB + j];
    }
    if (idx < N_EMB) {
        #pragma unroll
        for (int r = 0; r < NREP; r++) g_histR[r][idx] = 0.0f;
        float s = 0.0f;
        #pragma unroll
        for (int d = 0; d < EMB_D; d++) {
            float v = w[d * N_EMB + idx];
            s = __fadd_rn(s, __fmul_rn(v, v));
        }
        g_ww[idx] = s;
    }
}

// ---------------------------------------------------------------------------
// assign: R8 core + low-latency argmin tail (FMNMX/SEL, no @P guards)
// ---------------------------------------------------------------------------
extern __shared__ float smem_dyn[];

__global__ void __launch_bounds__(TPB, 1)
assign_kernel(const float* __restrict__ x,
              const float* __restrict__ cs_in,
              const float* __restrict__ ea_in,
              float* __restrict__ out) {
    float* w_s  = smem_dyn;                     // [512][64] j-major
    float* ww_s = smem_dyn + N_EMB * EMB_D;     // [512]
    __shared__ int s_chunk;
    __shared__ unsigned int s_rank;

    int tid  = threadIdx.x;
    int lane = tid & 31;
    int rep  = blockIdx.x & (NREP - 1);
    float* histR = g_histR[rep];
    float* esumR = g_esumR[rep];

    // Stage transposed weight once per CTA: coalesced, conflict-free
    {
        const float4* src = (const float4*)g_wt;
        float4* dst = (float4*)w_s;
        #pragma unroll
        for (int i = 0; i < (N_EMB * EMB_D / 4) / TPB; i++)
            dst[i * TPB + tid] = src[i * TPB + tid];
        ww_s[tid]       = g_ww[tid];
        ww_s[tid + 256] = g_ww[tid + 256];
    }

    for (;;) {
        __syncthreads();
        if (tid == 0) s_chunk = (int)atomicAdd(&g_work, 1u);
        __syncthreads();
        int c = s_chunk;
        if (c >= NCHUNK) break;

        // chunk = 512 consecutive tokens, never crosses a batch
        int t0 = c * TOKS_PER_CHUNK + tid;     // token A; token B = t0+256
        int b0 = t0 >> 12;
        int hw0 = t0 & (HWSZ - 1);
        const float* xa_p = x + (size_t)b0 * EMB_D * HWSZ + hw0;

        unsigned long long xpa[EMB_D / 2];
        unsigned long long xpb[EMB_D / 2];
        #pragma unroll
        for (int i = 0; i < EMB_D / 2; i++) {
            xpa[i] = pack2(xa_p[(2 * i) * HWSZ],       xa_p[(2 * i + 1) * HWSZ]);
            xpb[i] = pack2(xa_p[(2 * i) * HWSZ + 256], xa_p[(2 * i + 1) * HWSZ + 256]);
        }

        float bestA = 3.4e38f, bestB = 3.4e38f;
        int   biA = 0, biB = 0;

        #pragma unroll 1
        for (int j0 = 0; j0 < N_EMB; j0 += 2) {
            const ulonglong2* r0 = (const ulonglong2*)(w_s + (j0 + 0) * EMB_D);
            const ulonglong2* r1 = (const ulonglong2*)(w_s + (j0 + 1) * EMB_D);

            unsigned long long a0Ae = 0ULL, a0Ao = 0ULL, a0Be = 0ULL, a0Bo = 0ULL;
            unsigned long long a1Ae = 0ULL, a1Ao = 0ULL, a1Be = 0ULL, a1Bo = 0ULL;

            #pragma unroll
            for (int q = 0; q < EMB_D / 4; q++) {
                ulonglong2 v0 = r0[q];     // broadcast LDS.128
                ulonglong2 v1 = r1[q];
                unsigned long long xaE = xpa[2 * q], xaO = xpa[2 * q + 1];
                unsigned long long xbE = xpb[2 * q], xbO = xpb[2 * q + 1];
                a0Ae = ffma2(xaE, v0.x, a0Ae);  a0Ao = ffma2(xaO, v0.y, a0Ao);
                a0Be = ffma2(xbE, v0.x, a0Be);  a0Bo = ffma2(xbO, v0.y, a0Bo);
                a1Ae = ffma2(xaE, v1.x, a1Ae);  a1Ao = ffma2(xaO, v1.y, a1Ao);
                a1Be = ffma2(xbE, v1.x, a1Be);  a1Bo = ffma2(xbO, v1.y, a1Bo);
            }

            float lo, hi;
            float w0 = ww_s[j0], w1 = ww_s[j0 + 1];
            unpack2(fadd2(a0Ae, a0Ao), lo, hi);
            float d0A = __fmaf_rn(-2.0f, __fadd_rn(lo, hi), w0);
            unpack2(fadd2(a1Ae, a1Ao), lo, hi);
            float d1A = __fmaf_rn(-2.0f, __fadd_rn(lo, hi), w1);
            unpack2(fadd2(a0Be, a0Bo), lo, hi);
            float d0B = __fmaf_rn(-2.0f, __fadd_rn(lo, hi), w0);
            unpack2(fadd2(a1Be, a1Bo), lo, hi);
            float d1B = __fmaf_rn(-2.0f, __fadd_rn(lo, hi), w1);

            // low-latency argmin update (strict <, ascending j = first-min)
            amin_upd(d0A, j0,     bestA, biA);
            amin_upd(d1A, j0 + 1, bestA, biA);
            amin_upd(d0B, j0,     bestB, biB);
            amin_upd(d1B, j0 + 1, bestB, biB);
        }

        out[OFF_ARG + (size_t)t0]       = (float)biA;
        out[OFF_ARG + (size_t)t0 + 256] = (float)biB;

        // quantized result from smem codebook
        {
            float* ro = out + (size_t)b0 * EMB_D * HWSZ + hw0;
            const float4* wrowA = (const float4*)(w_s + biA * EMB_D);
            const float4* wrowB = (const float4*)(w_s + biB * EMB_D);
            #pragma unroll
            for (int i = 0; i < EMB_D / 4; i++) {
                float4 va = wrowA[i];
                float4 vb = wrowB[i];
                ro[(4 * i + 0) * HWSZ]       = va.x;
                ro[(4 * i + 1) * HWSZ]       = va.y;
                ro[(4 * i + 2) * HWSZ]       = va.z;
                ro[(4 * i + 3) * HWSZ]       = va.w;
                ro[(4 * i + 0) * HWSZ + 256] = vb.x;
                ro[(4 * i + 1) * HWSZ + 256] = vb.y;
                ro[(4 * i + 2) * HWSZ + 256] = vb.z;
                ro[(4 * i + 3) * HWSZ + 256] = vb.w;
            }
        }

        // hist: warp-aggregated (one add per distinct index per warp)
        {
            unsigned int mA = __match_any_sync(0xFFFFFFFFu, biA);
            if ((int)(__ffs(mA) - 1) == lane)
                atomicAdd(&histR[biA], (float)__popc(mA));
            unsigned int mB = __match_any_sync(0xFFFFFFFFu, biB);
            if ((int)(__ffs(mB) - 1) == lane)
                atomicAdd(&histR[biB], (float)__popc(mB));
        }

        // esum: replicated accumulators (hot-address chains / NREP)
        #pragma unroll
        for (int i = 0; i < EMB_D / 2; i++) {
            float lo, hi;
            unpack2(xpa[i], lo, hi);
            atomicAdd(&esumR[(2 * i)     * N_EMB + biA], lo);
            atomicAdd(&esumR[(2 * i + 1) * N_EMB + biA], hi);
            unpack2(xpb[i], lo, hi);
            atomicAdd(&esumR[(2 * i)     * N_EMB + biB], lo);
            atomicAdd(&esumR[(2 * i + 1) * N_EMB + biB], hi);
        }
    }

    // ------- merged finalize: last CTA does the EMA update -------
    __threadfence();
    __syncthreads();
    if (tid == 0) s_rank = atomicAdd(&g_done, 1u);
    __syncthreads();
    if (s_rank == GRID_A - 1) {
        float* red = smem_dyn;

        const float DEC  = 0.99f;
        const float OMD  = (float)(1.0 - 0.99);
        const float EPSF = (float)1e-5;
        const float NEPS = (float)(N_EMB * 1e-5);

        float ncs0, ncs1;
        {
            float n0 = 0.0f, n1 = 0.0f;
            #pragma unroll
            for (int r = 0; r < NREP; r++) {
                n0 += g_histR[r][tid];
                n1 += g_histR[r][tid + 256];
            }
            if (n0 == 0.0f) n0 = 1.0f;
            if (n1 == 0.0f) n1 = 1.0f;
            ncs0 = __fadd_rn(__fmul_rn(DEC, cs_in[tid]), __fmul_rn(OMD, n0));
            ncs1 = __fadd_rn(__fmul_rn(DEC, cs_in[tid + 256]), __fmul_rn(OMD, n1));
        }

        __syncthreads();
        red[tid] = ncs0 + ncs1;
        __syncthreads();
        #pragma unroll
        for (int s = 128; s > 0; s >>= 1) {
            if (tid < s) red[tid] += red[tid + s];
            __syncthreads();
        }
        float n = red[0];

        float csn0 = __fmul_rn(__fdiv_rn(__fadd_rn(ncs0, EPSF),
                                         __fadd_rn(n, NEPS)), n);
        float csn1 = __fmul_rn(__fdiv_rn(__fadd_rn(ncs1, EPSF),
                                         __fadd_rn(n, NEPS)), n);

        out[OFF_CS + tid]       = ncs0;
        out[OFF_CS + tid + 256] = ncs1;

        for (int d = 0; d < EMB_D; d++) {
            int i0 = d * N_EMB + tid;
            int i1 = i0 + 256;
            float s0 = 0.0f, s1 = 0.0f;
            #pragma unroll
            for (int r = 0; r < NREP; r++) {
                s0 += g_esumR[r][i0];
                s1 += g_esumR[r][i1];
            }
            float e0 = __fadd_rn(__fmul_rn(DEC, ea_in[i0]), __fmul_rn(OMD, s0));
            float e1 = __fadd_rn(__fmul_rn(DEC, ea_in[i1]), __fmul_rn(OMD, s1));
            out[OFF_EA + i0] = e0;
            out[OFF_EA + i1] = e1;
            out[OFF_W  + i0] = __fdiv_rn(e0, csn0);
            out[OFF_W  + i1] = __fdiv_rn(e1, csn1);
        }
    }
}

// ---------------------------------------------------------------------------
extern "C" void kernel_launch(void* const* d_in, const int* in_sizes, int n_in,
                              void* d_out, int out_size) {
    const float* x  = (const float*)d_in[0];
    const float* w  = (const float*)d_in[1];
    const float* cs = (const float*)d_in[2];
    const float* ea = (const float*)d_in[3];
    float* out = (float*)d_out;

    cudaFuncSetAttribute(assign_kernel,
                         cudaFuncAttributeMaxDynamicSharedMemorySize, SMEM_BYTES);

    prep_kernel<<<128, 256>>>(w);
    assign_kernel<<<GRID_A, TPB, SMEM_BYTES>>>(x, cs, ea, out);
}